// round 12
// baseline (speedup 1.0000x reference)
#include <cuda_runtime.h>
#include <cstdint>
#include <cstddef>

#define B_   32
#define C_   256
#define HW_  3136
#define OC_  256
#define PW   58                            // padded width/height
#define PQ   3492                          // 58*58 + 128 tail pad rows

// ---------------- scratch (device globals) ----------------
__device__ float d_mu[B_ * 8];
__device__ float d_rs[B_ * 8];
__device__ float d_scale[OC_];             // alpha_oc * a_c / 255
__device__ unsigned char d_hq[(size_t)B_ * PQ * 256];   // padded NHWC u8
__device__ signed char  d_ws[9 * 256 * 256];            // [tap][oc][ic] in {-1,0,1}

// ======================= PTX helpers =======================
__device__ __forceinline__ uint32_t smem_u32(const void* p) {
    uint32_t a;
    asm("{ .reg .u64 t; cvta.to.shared.u64 t, %1; cvt.u32.u64 %0, t; }" : "=r"(a) : "l"(p));
    return a;
}
#define CP16(dst, src) \
    asm volatile("cp.async.cg.shared.global [%0], [%1], 16;" :: "r"(dst), "l"(src) : "memory")
#define CP_COMMIT() asm volatile("cp.async.commit_group;" ::: "memory")
#define CP_WAIT1()  asm volatile("cp.async.wait_group 1;" ::: "memory")

__device__ __forceinline__ void ldsm4(uint32_t* r, uint32_t addr) {
    asm volatile("ldmatrix.sync.aligned.m8n8.x4.shared.b16 {%0,%1,%2,%3}, [%4];"
                 : "=r"(r[0]), "=r"(r[1]), "=r"(r[2]), "=r"(r[3]) : "r"(addr));
}
__device__ __forceinline__ void ldsm2(uint32_t* r, uint32_t addr) {
    asm volatile("ldmatrix.sync.aligned.m8n8.x2.shared.b16 {%0,%1}, [%2];"
                 : "=r"(r[0]), "=r"(r[1]) : "r"(addr));
}
__device__ __forceinline__ void mma_u8s8(int* c, const uint32_t* a, const uint32_t* b) {
    asm volatile(
        "mma.sync.aligned.m16n8k32.row.col.s32.u8.s8.s32 "
        "{%0,%1,%2,%3}, {%4,%5,%6,%7}, {%8,%9}, {%0,%1,%2,%3};"
        : "+r"(c[0]), "+r"(c[1]), "+r"(c[2]), "+r"(c[3])
        : "r"(a[0]), "r"(a[1]), "r"(a[2]), "r"(a[3]), "r"(b[0]), "r"(b[1]));
}
__device__ __forceinline__ int dp4a_us(unsigned a, unsigned b, int c) {
    int d;
    asm("dp4a.u32.s32 %0, %1, %2, %3;" : "=r"(d) : "r"(a), "r"(b), "r"(c));
    return d;
}

// ---------------- kernel 1: ternarize weights -> s8 [tap][oc][ic] ----------------
__global__ void tern_kernel(const float* __restrict__ w,
                            const float* __restrict__ a_ptr) {
    int oc = blockIdx.x, tid = threadIdx.x;
    const float* wp = w + (size_t)oc * 2304;
    __shared__ float red[256], red2[256];
    __shared__ float t_sh;

    float s = 0.f;
    for (int i = tid; i < 2304; i += 256) s += fabsf(wp[i]);
    red[tid] = s;
    __syncthreads();
    for (int o = 128; o; o >>= 1) {
        if (tid < o) red[tid] += red[tid + o];
        __syncthreads();
    }
    if (tid == 0) t_sh = 0.05f * red[0] / 2304.0f;
    __syncthreads();
    float t = t_sh;

    float sa = 0.f, sm = 0.f;
    for (int i = tid; i < 2304; i += 256) {
        float aw = fabsf(wp[i]);
        if (aw > t) { sa += aw; sm += 1.f; }
    }
    red[tid] = sa; red2[tid] = sm;
    __syncthreads();
    for (int o = 128; o; o >>= 1) {
        if (tid < o) { red[tid] += red[tid + o]; red2[tid] += red2[tid + o]; }
        __syncthreads();
    }
    if (tid == 0) {
        float alpha = red[0] / (red2[0] + 1e-8f);
        float a_c = fmaxf(a_ptr[0], 0.f) + 1e-8f;
        d_scale[oc] = alpha * a_c / 255.0f;
    }
    for (int i = tid; i < 2304; i += 256) {
        float wv = wp[i];
        signed char q = (fabsf(wv) > t) ? (wv > 0.f ? (signed char)1 : (signed char)-1)
                                        : (signed char)0;
        int ic = i / 9, k = i - ic * 9;    // tap = ky*3+kx
        d_ws[((size_t)k * 256 + oc) * 256 + ic] = q;
    }
}

// ---------------- kernel 2: GroupNorm statistics ----------------
__global__ void gn_stats_kernel(const float* __restrict__ x) {
    int bg = blockIdx.x;
    int b = bg >> 3, g = bg & 7;
    const float4* xp = (const float4*)(x + ((size_t)b * C_ + (size_t)g * 32) * HW_);
    const int N4 = 32 * HW_ / 4;
    int tid = threadIdx.x;
    float s = 0.f, s2 = 0.f;
#pragma unroll 4
    for (int i = tid; i < N4; i += 512) {
        float4 v = xp[i];
        s += v.x + v.y + v.z + v.w;
        s2 += v.x * v.x + v.y * v.y + v.z * v.z + v.w * v.w;
    }
    __shared__ float r1[512], r2[512];
    r1[tid] = s; r2[tid] = s2;
    __syncthreads();
    for (int o = 256; o; o >>= 1) {
        if (tid < o) { r1[tid] += r1[tid + o]; r2[tid] += r2[tid + o]; }
        __syncthreads();
    }
    if (tid == 0) {
        const float N = (float)(32 * HW_);
        float mu = r1[0] / N;
        float var = r2[0] / N - mu * mu;
        d_mu[bg] = mu;
        d_rs[bg] = rsqrtf(var + 1e-5f);
    }
}

// ---------------- kernel 3: GN + ReLU^2 + PACT quant + pad-zero (fused) ----------
__global__ void quant_kernel(const float* __restrict__ x,
                             const float* __restrict__ gamma,
                             const float* __restrict__ beta,
                             const float* __restrict__ a_ptr) {
    int b = blockIdx.z;
    int tx = threadIdx.x, ty = threadIdx.y;
    int tid = ty * 32 + tx;

    if (blockIdx.x >= 98) {                // pad-zero blocks
        if (blockIdx.y != 0) return;
        int slot = (blockIdx.x - 98) * 30 + (tid >> 3);
        if (slot >= 356) return;
        int r;
        if (slot < 58)        r = slot;                      // y=0
        else if (slot < 116)  r = 3306 + (slot - 58);        // y=57
        else if (slot < 172)  r = (slot - 115) * PW;         // x=0, y=1..56
        else if (slot < 228)  r = (slot - 171) * PW + 57;    // x=57, y=1..56
        else                  r = 3364 + (slot - 228);       // tail overread rows
        uint4* dst = (uint4*)(d_hq + ((size_t)b * PQ + r) * 256 + (tid & 7) * 32);
        dst[0] = make_uint4(0, 0, 0, 0);
        dst[1] = make_uint4(0, 0, 0, 0);
        return;
    }

    __shared__ unsigned char tile[32][33];
    int c0 = blockIdx.y * 32;
    int p0 = blockIdx.x * 32;

    float a_c = fmaxf(a_ptr[0], 0.f) + 1e-8f;
    float S = 255.f / a_c;
    float mu = d_mu[b * 8 + blockIdx.y];
    float rs = d_rs[b * 8 + blockIdx.y];

#pragma unroll
    for (int i = 0; i < 4; i++) {
        int cl = ty + i * 8;
        int c = c0 + cl;
        float v = x[((size_t)b * C_ + c) * HW_ + p0 + tx];
        float xn = (v - mu) * rs * gamma[c] + beta[c];
        float r = fmaxf(xn, 0.f);
        float h = r * r;
        float yv = fminf(h, a_c);
        tile[cl][tx] = (unsigned char)(int)rintf(yv * S);
    }
    __syncthreads();
#pragma unroll
    for (int i = 0; i < 4; i++) {
        int p = p0 + ty + i * 8;           // valid pixel 0..3135
        int y = p / 56, xx = p - y * 56;
        size_t r = (size_t)(y + 1) * PW + (xx + 1);
        d_hq[((size_t)b * PQ + r) * 256 + c0 + tx] = tile[tx][ty + i * 8];
    }
}

// ---------------- kernel 4: hybrid IMMA + dp4a conv, 128x64 tiles, K=128/stage --
// 3200 CTAs: b = bid/100, n0 = ((bid%100)/25)*64, q0 = ((bid%100)%25)*128.
// Role: (bid % 15) < 8 -> IMMA, else dp4a. 18 stages of K=128B, NST=3, 3 CTAs/SM.
// smem/stage: A 128x128 (16384) + B 64x128 (8192) = 24576; rows pitch 128,
// 8x16B chunks swizzled by key(row) = (row ^ (row>>3)) & 7.
#define NST 3
#define STAGE_B 24576
#define SMEM_CONV (NST * STAGE_B)

__global__ void __launch_bounds__(256, 3)
conv_mma_kernel(const float* __restrict__ bias, float* __restrict__ out) {
    extern __shared__ char smem[];
    uint32_t sbase = smem_u32(smem);
    int tid = threadIdx.x;
    int wid = tid >> 5, lane = tid & 31;
    int bid = blockIdx.x;
    int b = bid / 100;
    int rem = bid - b * 100;
    int n0 = (rem / 25) * 64;
    int q0 = (rem % 25) * 128;
    bool isIMMA = (bid % 15) < 8;

    // loaders: tid<128 -> A row tid (8x16B); tid in [128,192) -> B row tid-128
    bool isA = tid < 128;
    bool isLd = tid < 192;
    int lrow = isA ? tid : tid - 128;
    int lkey = (lrow ^ (lrow >> 3)) & 7;
    uint32_t sdst0 = sbase + (isA ? 0u : 16384u) + (uint32_t)lrow * 128u;

    const char* gbase;
    if (isA) {
        int q = q0 + lrow;                 // tail tiles read zeroed pad rows
        int y = q / 56, xx = q - y * 56;
        gbase = (const char*)(d_hq + ((size_t)b * PQ + (size_t)(y * PW + xx)) * 256);
    } else {
        gbase = (const char*)(d_ws + (size_t)(n0 + lrow) * 256);
    }

    // stage s (0..17): tap = s>>1, half = s&1 (128B of the 256-ic row)
    auto issue = [&](int s) {
        int st = s % NST;
        if (isLd) {
            int tap = s >> 1, half = s & 1;
            const char* g;
            if (isA) {
                int ky = tap / 3, kx = tap - ky * 3;
                g = gbase + (size_t)(ky * PW + kx) * 256 + half * 128;
            } else {
                g = gbase + (size_t)tap * 65536 + half * 128;
            }
            uint32_t d = sdst0 + (uint32_t)st * STAGE_B;
#pragma unroll
            for (int c = 0; c < 8; c++)
                CP16(d + (uint32_t)((c ^ lkey) & 7) * 16u, g + c * 16);
        }
        CP_COMMIT();
    };

    int acc[32];
#pragma unroll
    for (int i = 0; i < 32; i++) acc[i] = 0;

    // ---- IMMA geometry: warp tile 64x16 ----
    int warp_m = wid >> 2, warp_n = wid & 3;
    int grp = lane >> 3, r8 = lane & 7;
    uint32_t a_base[4]; int a_key[4]; int a_cb = grp >> 1;
#pragma unroll
    for (int t = 0; t < 4; t++) {
        int row = warp_m * 64 + t * 16 + (grp & 1) * 8 + r8;
        a_base[t] = sbase + (uint32_t)row * 128u;
        a_key[t] = (row ^ (row >> 3)) & 7;
    }
    int bl = lane & 15;
    uint32_t b_base[2]; int b_key[2]; int b_cb = bl >> 3;
#pragma unroll
    for (int u = 0; u < 2; u++) {
        int row = warp_n * 16 + u * 8 + (bl & 7);
        b_base[u] = sbase + 16384u + (uint32_t)row * 128u;
        b_key[u] = (row ^ (row >> 3)) & 7;
    }

    // ---- dp4a geometry: 8 pixels x 4 ocs per thread ----
    int tm = tid >> 4, tn = tid & 15;
    const char* sA = smem;
    const char* sB = smem + 16384;
    int bkey[4];
#pragma unroll
    for (int j = 0; j < 4; j++) {
        int row = tn * 4 + j;
        bkey[j] = (row ^ (row >> 3)) & 7;
    }

    issue(0); issue(1);

#pragma unroll 1
    for (int s = 0; s < 18; s++) {
        int st = s % NST;
        CP_WAIT1();
        __syncthreads();
        if (s + 2 < 18) issue(s + 2);
        else CP_COMMIT();
        uint32_t so = (uint32_t)st * STAGE_B;

        if (isIMMA) {
#pragma unroll
            for (int ks = 0; ks < 4; ks++) {
                uint32_t afr[4][4], bfr[2][2];
#pragma unroll
                for (int t = 0; t < 4; t++) {
                    uint32_t c = (uint32_t)(((ks * 2 + a_cb) ^ a_key[t]) & 7) * 16u;
                    ldsm4(afr[t], a_base[t] + so + c);
                }
#pragma unroll
                for (int u = 0; u < 2; u++) {
                    uint32_t c = (uint32_t)(((ks * 2 + b_cb) ^ b_key[u]) & 7) * 16u;
                    ldsm2(bfr[u], b_base[u] + so + c);
                }
#pragma unroll
                for (int t = 0; t < 4; t++)
#pragma unroll
                    for (int u = 0; u < 2; u++)
                        mma_u8s8(&acc[(t * 2 + u) * 4], afr[t], bfr[u]);
            }
        } else {
            const char* pA = sA + so;
            const char* pB = sB + so;
#pragma unroll 1
            for (int kb = 0; kb < 8; kb++) {
                uint4 av[8];
#pragma unroll
                for (int i = 0; i < 8; i++) {
                    // row tm*8+i -> key = (i ^ tm) & 7
                    uint32_t ca = (uint32_t)((kb ^ i ^ tm) & 7) * 16u;
                    av[i] = *(const uint4*)(pA + (tm * 8 + i) * 128 + ca);
                }
#pragma unroll
                for (int j = 0; j < 4; j++) {
                    uint32_t cb = (uint32_t)((kb ^ bkey[j]) & 7) * 16u;
                    uint4 bv = *(const uint4*)(pB + (tn * 4 + j) * 128 + cb);
#pragma unroll
                    for (int i = 0; i < 8; i++) {
                        int v = acc[i * 4 + j];
                        v = dp4a_us(av[i].x, bv.x, v);
                        v = dp4a_us(av[i].y, bv.y, v);
                        v = dp4a_us(av[i].z, bv.z, v);
                        v = dp4a_us(av[i].w, bv.w, v);
                        acc[i * 4 + j] = v;
                    }
                }
            }
        }
    }

    // ---------------- epilogue: stage via smem, coalesced NCHW stores --------
    __syncthreads();
    int* sep = (int*)smem;                // [64 oc][pitch 132]
    if (isIMMA) {
#pragma unroll
        for (int t = 0; t < 4; t++) {
            int m = warp_m * 64 + t * 16 + (lane >> 2);
#pragma unroll
            for (int u = 0; u < 2; u++) {
                int n = warp_n * 16 + u * 8 + 2 * (lane & 3);
                const int* a4 = &acc[(t * 2 + u) * 4];
                sep[n * 132 + m]           = a4[0];
                sep[(n + 1) * 132 + m]     = a4[1];
                sep[n * 132 + m + 8]       = a4[2];
                sep[(n + 1) * 132 + m + 8] = a4[3];
            }
        }
    } else {
#pragma unroll
        for (int j = 0; j < 4; j++)
#pragma unroll
            for (int i = 0; i < 8; i++)
                sep[(tn * 4 + j) * 132 + tm * 8 + i] = acc[i * 4 + j];
    }
    __syncthreads();

#pragma unroll 1
    for (int i = 0; i < 8; i++) {
        int ol = wid + i * 8;
        int oc = n0 + ol;
        float sc = d_scale[oc];
        float bv = __ldg(&bias[oc]);
        float* orow = out + ((size_t)(b * OC_ + oc)) * HW_ + q0;
#pragma unroll
        for (int qc = 0; qc < 4; qc++) {
            int m = qc * 32 + lane;
            if (q0 + m < HW_)
                orow[m] = fmaf(sc, (float)sep[ol * 132 + m], bv);
        }
    }
}

// ---------------- launch (conv is the 4th launch for ncu capture) ----------------
extern "C" void kernel_launch(void* const* d_in, const int* in_sizes, int n_in,
                              void* d_out, int out_size) {
    const float* x     = (const float*)d_in[0];
    const float* gamma = (const float*)d_in[1];
    const float* beta  = (const float*)d_in[2];
    const float* a     = (const float*)d_in[3];
    const float* wfp   = (const float*)d_in[4];
    const float* bias  = (const float*)d_in[5];
    float* out = (float*)d_out;
    (void)in_sizes; (void)n_in; (void)out_size;

    tern_kernel<<<OC_, 256>>>(wfp, a);
    gn_stats_kernel<<<B_ * 8, 512>>>(x);
    quant_kernel<<<dim3(110, 8, B_), dim3(32, 8)>>>(x, gamma, beta, a);

    cudaFuncSetAttribute(conv_mma_kernel,
                         cudaFuncAttributeMaxDynamicSharedMemorySize, SMEM_CONV);
    conv_mma_kernel<<<3200, 256, SMEM_CONV>>>(bias, out);
}

// round 13
// speedup vs baseline: 1.0680x; 1.0680x over previous
#include <cuda_runtime.h>
#include <cstdint>
#include <cstddef>

#define B_   32
#define C_   256
#define HW_  3136
#define OC_  256
#define PW   58                            // padded width/height
#define PQ   3492                          // 58*58 + 128 tail pad rows

// ---------------- scratch (device globals) ----------------
__device__ float d_mu[B_ * 8];
__device__ float d_rs[B_ * 8];
__device__ float d_scale[OC_];             // alpha_oc * a_c / 255
__device__ unsigned char d_hq[(size_t)B_ * PQ * 256];   // padded NHWC u8
__device__ signed char  d_ws[9 * 256 * 256];            // [tap][oc][ic] in {-1,0,1}

// ======================= PTX helpers =======================
__device__ __forceinline__ uint32_t smem_u32(const void* p) {
    uint32_t a;
    asm("{ .reg .u64 t; cvta.to.shared.u64 t, %1; cvt.u32.u64 %0, t; }" : "=r"(a) : "l"(p));
    return a;
}
#define CP16(dst, src) \
    asm volatile("cp.async.cg.shared.global [%0], [%1], 16;" :: "r"(dst), "l"(src) : "memory")
#define CP_COMMIT() asm volatile("cp.async.commit_group;" ::: "memory")
#define CP_WAIT3()  asm volatile("cp.async.wait_group 3;" ::: "memory")

__device__ __forceinline__ void ldsm4(uint32_t* r, uint32_t addr) {
    asm volatile("ldmatrix.sync.aligned.m8n8.x4.shared.b16 {%0,%1,%2,%3}, [%4];"
                 : "=r"(r[0]), "=r"(r[1]), "=r"(r[2]), "=r"(r[3]) : "r"(addr));
}
__device__ __forceinline__ void ldsm2(uint32_t* r, uint32_t addr) {
    asm volatile("ldmatrix.sync.aligned.m8n8.x2.shared.b16 {%0,%1}, [%2];"
                 : "=r"(r[0]), "=r"(r[1]) : "r"(addr));
}
__device__ __forceinline__ void mma_u8s8(int* c, const uint32_t* a, const uint32_t* b) {
    asm volatile(
        "mma.sync.aligned.m16n8k32.row.col.s32.u8.s8.s32 "
        "{%0,%1,%2,%3}, {%4,%5,%6,%7}, {%8,%9}, {%0,%1,%2,%3};"
        : "+r"(c[0]), "+r"(c[1]), "+r"(c[2]), "+r"(c[3])
        : "r"(a[0]), "r"(a[1]), "r"(a[2]), "r"(a[3]), "r"(b[0]), "r"(b[1]));
}
__device__ __forceinline__ int dp4a_us(unsigned a, unsigned b, int c) {
    int d;
    asm("dp4a.u32.s32 %0, %1, %2, %3;" : "=r"(d) : "r"(a), "r"(b), "r"(c));
    return d;
}

// ---------------- kernel 1: ternarize weights -> s8 [tap][oc][ic] ----------------
__global__ void tern_kernel(const float* __restrict__ w,
                            const float* __restrict__ a_ptr) {
    int oc = blockIdx.x, tid = threadIdx.x;
    const float* wp = w + (size_t)oc * 2304;
    __shared__ float red[256], red2[256];
    __shared__ float t_sh;

    float s = 0.f;
    for (int i = tid; i < 2304; i += 256) s += fabsf(wp[i]);
    red[tid] = s;
    __syncthreads();
    for (int o = 128; o; o >>= 1) {
        if (tid < o) red[tid] += red[tid + o];
        __syncthreads();
    }
    if (tid == 0) t_sh = 0.05f * red[0] / 2304.0f;
    __syncthreads();
    float t = t_sh;

    float sa = 0.f, sm = 0.f;
    for (int i = tid; i < 2304; i += 256) {
        float aw = fabsf(wp[i]);
        if (aw > t) { sa += aw; sm += 1.f; }
    }
    red[tid] = sa; red2[tid] = sm;
    __syncthreads();
    for (int o = 128; o; o >>= 1) {
        if (tid < o) { red[tid] += red[tid + o]; red2[tid] += red2[tid + o]; }
        __syncthreads();
    }
    if (tid == 0) {
        float alpha = red[0] / (red2[0] + 1e-8f);
        float a_c = fmaxf(a_ptr[0], 0.f) + 1e-8f;
        d_scale[oc] = alpha * a_c / 255.0f;
    }
    for (int i = tid; i < 2304; i += 256) {
        float wv = wp[i];
        signed char q = (fabsf(wv) > t) ? (wv > 0.f ? (signed char)1 : (signed char)-1)
                                        : (signed char)0;
        int ic = i / 9, k = i - ic * 9;    // tap = ky*3+kx
        d_ws[((size_t)k * 256 + oc) * 256 + ic] = q;
    }
}

// ---------------- kernel 2: GroupNorm statistics ----------------
__global__ void gn_stats_kernel(const float* __restrict__ x) {
    int bg = blockIdx.x;
    int b = bg >> 3, g = bg & 7;
    const float4* xp = (const float4*)(x + ((size_t)b * C_ + (size_t)g * 32) * HW_);
    const int N4 = 32 * HW_ / 4;
    int tid = threadIdx.x;
    float s = 0.f, s2 = 0.f;
#pragma unroll 4
    for (int i = tid; i < N4; i += 512) {
        float4 v = xp[i];
        s += v.x + v.y + v.z + v.w;
        s2 += v.x * v.x + v.y * v.y + v.z * v.z + v.w * v.w;
    }
    __shared__ float r1[512], r2[512];
    r1[tid] = s; r2[tid] = s2;
    __syncthreads();
    for (int o = 256; o; o >>= 1) {
        if (tid < o) { r1[tid] += r1[tid + o]; r2[tid] += r2[tid + o]; }
        __syncthreads();
    }
    if (tid == 0) {
        const float N = (float)(32 * HW_);
        float mu = r1[0] / N;
        float var = r2[0] / N - mu * mu;
        d_mu[bg] = mu;
        d_rs[bg] = rsqrtf(var + 1e-5f);
    }
}

// ---------------- kernel 3: GN + ReLU^2 + PACT quant + pad-zero (fused) ----------
__global__ void quant_kernel(const float* __restrict__ x,
                             const float* __restrict__ gamma,
                             const float* __restrict__ beta,
                             const float* __restrict__ a_ptr) {
    int b = blockIdx.z;
    int tx = threadIdx.x, ty = threadIdx.y;
    int tid = ty * 32 + tx;

    if (blockIdx.x >= 98) {                // pad-zero blocks
        if (blockIdx.y != 0) return;
        int slot = (blockIdx.x - 98) * 30 + (tid >> 3);
        if (slot >= 356) return;
        int r;
        if (slot < 58)        r = slot;                      // y=0
        else if (slot < 116)  r = 3306 + (slot - 58);        // y=57
        else if (slot < 172)  r = (slot - 115) * PW;         // x=0, y=1..56
        else if (slot < 228)  r = (slot - 171) * PW + 57;    // x=57, y=1..56
        else                  r = 3364 + (slot - 228);       // tail overread rows
        uint4* dst = (uint4*)(d_hq + ((size_t)b * PQ + r) * 256 + (tid & 7) * 32);
        dst[0] = make_uint4(0, 0, 0, 0);
        dst[1] = make_uint4(0, 0, 0, 0);
        return;
    }

    __shared__ unsigned char tile[32][33];
    int c0 = blockIdx.y * 32;
    int p0 = blockIdx.x * 32;

    float a_c = fmaxf(a_ptr[0], 0.f) + 1e-8f;
    float S = 255.f / a_c;
    float mu = d_mu[b * 8 + blockIdx.y];
    float rs = d_rs[b * 8 + blockIdx.y];

#pragma unroll
    for (int i = 0; i < 4; i++) {
        int cl = ty + i * 8;
        int c = c0 + cl;
        float v = x[((size_t)b * C_ + c) * HW_ + p0 + tx];
        float xn = (v - mu) * rs * gamma[c] + beta[c];
        float r = fmaxf(xn, 0.f);
        float h = r * r;
        float yv = fminf(h, a_c);
        tile[cl][tx] = (unsigned char)(int)rintf(yv * S);
    }
    __syncthreads();
#pragma unroll
    for (int i = 0; i < 4; i++) {
        int p = p0 + ty + i * 8;           // valid pixel 0..3135
        int y = p / 56, xx = p - y * 56;
        size_t r = (size_t)(y + 1) * PW + (xx + 1);
        d_hq[((size_t)b * PQ + r) * 256 + c0 + tx] = tile[tx][ty + i * 8];
    }
}

// ---------------- kernel 4: hybrid IMMA + dp4a conv, 128x64 tiles -------------
// 3200 CTAs: b = bid/100, n0 = ((bid%100)/25)*64, q0 = ((bid%100)%25)*128.
// Role: (bid % 3) < 2 -> IMMA (2133 tiles), else dp4a (1067) — total-work optimum
// for measured T_dp4a/T_imma = 2. 3 CTAs/SM; NST=5, K=64/stage (R11 structure).
#define NST 5
#define STAGE_B 15360
#define SMEM_CONV (NST * STAGE_B)

__global__ void __launch_bounds__(256, 3)
conv_mma_kernel(const float* __restrict__ bias, float* __restrict__ out) {
    extern __shared__ char smem[];
    uint32_t sbase = smem_u32(smem);
    int tid = threadIdx.x;
    int wid = tid >> 5, lane = tid & 31;
    int bid = blockIdx.x;
    int b = bid / 100;
    int rem = bid - b * 100;
    int n0 = (rem / 25) * 64;
    int q0 = (rem % 25) * 128;
    bool isIMMA = (bid % 3) < 2;

    // loaders: tid<128 -> A row tid; tid in [128,192) -> B row tid-128; else none
    bool isA = tid < 128;
    bool isLd = tid < 192;
    int lrow = isA ? tid : tid - 128;
    int lsw = (lrow >> 3) & 3;
    uint32_t sdst0 = sbase + (isA ? 0u : 10240u) + (uint32_t)lrow * 80u;

    const char* gbase;
    if (isA) {
        int q = q0 + lrow;                 // tail tiles read zeroed pad rows
        int y = q / 56, xx = q - y * 56;
        gbase = (const char*)(d_hq + ((size_t)b * PQ + (size_t)(y * PW + xx)) * 256);
    } else {
        gbase = (const char*)(d_ws + (size_t)(n0 + lrow) * 256);
    }

    auto issue = [&](int s) {
        int st = s % NST;
        if (isLd) {
            int tap = s >> 2, cc = s & 3;
            const char* g;
            if (isA) {
                int ky = tap / 3, kx = tap - ky * 3;
                g = gbase + (size_t)(ky * PW + kx) * 256 + cc * 64;
            } else {
                g = gbase + (size_t)tap * 65536 + cc * 64;
            }
            uint32_t d = sdst0 + (uint32_t)st * STAGE_B;
            CP16(d + ((0 ^ lsw) & 3) * 16, g);
            CP16(d + ((1 ^ lsw) & 3) * 16, g + 16);
            CP16(d + ((2 ^ lsw) & 3) * 16, g + 32);
            CP16(d + ((3 ^ lsw) & 3) * 16, g + 48);
        }
        CP_COMMIT();
    };

    // 32 accumulator regs (disjoint role lifetimes)
    int acc[32];
#pragma unroll
    for (int i = 0; i < 32; i++) acc[i] = 0;

    // ---- IMMA geometry: warp tile 64x16 ----
    int warp_m = wid >> 2, warp_n = wid & 3;
    int grp = lane >> 3, r8 = lane & 7;
    uint32_t a_base[4]; int a_swz[4]; int a_cb = grp >> 1;
#pragma unroll
    for (int t = 0; t < 4; t++) {
        int row = warp_m * 64 + t * 16 + (grp & 1) * 8 + r8;
        a_base[t] = sbase + (uint32_t)row * 80u;
        a_swz[t] = (row >> 3) & 3;
    }
    int bl = lane & 15;
    uint32_t b_base[2]; int b_swz[2]; int b_cb = bl >> 3;
#pragma unroll
    for (int u = 0; u < 2; u++) {
        int row = warp_n * 16 + u * 8 + (bl & 7);
        b_base[u] = sbase + 10240u + (uint32_t)row * 80u;
        b_swz[u] = (row >> 3) & 3;
    }

    // ---- dp4a geometry: 8 pixels x 4 ocs per thread ----
    int tm = tid >> 4, tn = tid & 15;      // pix rows tm*8+i, oc rows tn*4+j
    int tns = tn >> 1;                     // (tn*4+j)>>3 for j<4
    const char* sA = smem;
    const char* sB = smem + 10240;

    issue(0); issue(1); issue(2); issue(3);

#pragma unroll 1
    for (int s = 0; s < 36; s++) {
        int st = s % NST;
        CP_WAIT3();
        __syncthreads();
        if (s + 4 < 36) issue(s + 4);
        else CP_COMMIT();
        uint32_t so = (uint32_t)st * STAGE_B;

        if (isIMMA) {
#pragma unroll
            for (int ks = 0; ks < 2; ks++) {
                uint32_t afr[4][4], bfr[2][2];
#pragma unroll
                for (int t = 0; t < 4; t++) {
                    uint32_t c = (uint32_t)(((ks * 2 + a_cb) ^ a_swz[t]) & 3) * 16u;
                    ldsm4(afr[t], a_base[t] + so + c);
                }
#pragma unroll
                for (int u = 0; u < 2; u++) {
                    uint32_t c = (uint32_t)(((ks * 2 + b_cb) ^ b_swz[u]) & 3) * 16u;
                    ldsm2(bfr[u], b_base[u] + so + c);
                }
#pragma unroll
                for (int t = 0; t < 4; t++)
#pragma unroll
                    for (int u = 0; u < 2; u++)
                        mma_u8s8(&acc[(t * 2 + u) * 4], afr[t], bfr[u]);
            }
        } else {
            const char* pA = sA + so;
            const char* pB = sB + so;
#pragma unroll 1
            for (int kb = 0; kb < 4; kb++) {
                uint32_t ca = (uint32_t)((kb ^ tm) & 3) * 16u;    // av rows>>3 == tm
                uint32_t cb = (uint32_t)((kb ^ tns) & 3) * 16u;   // bv rows>>3 == tn>>1
                uint4 av[8];
#pragma unroll
                for (int i = 0; i < 8; i++)
                    av[i] = *(const uint4*)(pA + (tm * 8 + i) * 80 + ca);
#pragma unroll
                for (int j = 0; j < 4; j++) {
                    uint4 bv = *(const uint4*)(pB + (tn * 4 + j) * 80 + cb);
#pragma unroll
                    for (int i = 0; i < 8; i++) {
                        int v = acc[i * 4 + j];
                        v = dp4a_us(av[i].x, bv.x, v);
                        v = dp4a_us(av[i].y, bv.y, v);
                        v = dp4a_us(av[i].z, bv.z, v);
                        v = dp4a_us(av[i].w, bv.w, v);
                        acc[i * 4 + j] = v;
                    }
                }
            }
        }
    }

    // ---------------- epilogue: stage via smem, coalesced NCHW stores --------
    __syncthreads();
    int* sep = (int*)smem;                // [64 oc][pitch 132]
    if (isIMMA) {
#pragma unroll
        for (int t = 0; t < 4; t++) {
            int m = warp_m * 64 + t * 16 + (lane >> 2);
#pragma unroll
            for (int u = 0; u < 2; u++) {
                int n = warp_n * 16 + u * 8 + 2 * (lane & 3);
                const int* a4 = &acc[(t * 2 + u) * 4];
                sep[n * 132 + m]           = a4[0];
                sep[(n + 1) * 132 + m]     = a4[1];
                sep[n * 132 + m + 8]       = a4[2];
                sep[(n + 1) * 132 + m + 8] = a4[3];
            }
        }
    } else {
#pragma unroll
        for (int j = 0; j < 4; j++)
#pragma unroll
            for (int i = 0; i < 8; i++)
                sep[(tn * 4 + j) * 132 + tm * 8 + i] = acc[i * 4 + j];
    }
    __syncthreads();

#pragma unroll 1
    for (int i = 0; i < 8; i++) {
        int ol = wid + i * 8;
        int oc = n0 + ol;
        float sc = d_scale[oc];
        float bv = __ldg(&bias[oc]);
        float* orow = out + ((size_t)(b * OC_ + oc)) * HW_ + q0;
#pragma unroll
        for (int qc = 0; qc < 4; qc++) {
            int m = qc * 32 + lane;
            if (q0 + m < HW_)
                orow[m] = fmaf(sc, (float)sep[ol * 132 + m], bv);
        }
    }
}

// ---------------- launch (conv is the 4th launch for ncu capture) ----------------
extern "C" void kernel_launch(void* const* d_in, const int* in_sizes, int n_in,
                              void* d_out, int out_size) {
    const float* x     = (const float*)d_in[0];
    const float* gamma = (const float*)d_in[1];
    const float* beta  = (const float*)d_in[2];
    const float* a     = (const float*)d_in[3];
    const float* wfp   = (const float*)d_in[4];
    const float* bias  = (const float*)d_in[5];
    float* out = (float*)d_out;
    (void)in_sizes; (void)n_in; (void)out_size;

    tern_kernel<<<OC_, 256>>>(wfp, a);
    gn_stats_kernel<<<B_ * 8, 512>>>(x);
    quant_kernel<<<dim3(110, 8, B_), dim3(32, 8)>>>(x, gamma, beta, a);

    cudaFuncSetAttribute(conv_mma_kernel,
                         cudaFuncAttributeMaxDynamicSharedMemorySize, SMEM_CONV);
    conv_mma_kernel<<<3200, 256, SMEM_CONV>>>(bias, out);
}